// round 8
// baseline (speedup 1.0000x reference)
#include <cuda_runtime.h>
#include <cstdint>

// Problem constants
#define B_    256
#define T_    2048
#define F_    64
#define H_    512
#define C_    128

// Partitioning: 32 j-chunks (16 h-units each) x 4 batch-chunks (64 batches) = 128 CTAs
#define NJ    32
#define NCTA  128
#define NTHR  256
#define JT    16      // h-units per CTA (=> 64 gate rows)
#define BT    64      // batches per CTA

// SMEM strides
#define WS_STR   72    // weight rows: 64 used + 8 pad (floats)
#define PAN2_STR 132   // duplicated panel row: 128 data + 4 pad (floats)
#define HN_STR   68

// ---------------- device globals (static scratch; zero-initialized at load) --
__device__ float g_hT[2][H_][B_];            // transposed h state, double buffered
__device__ float g_part[2][NJ][B_][C_];      // decoder partial logits, parity buffered
__device__ unsigned int g_count = 0;
__device__ volatile unsigned int g_sense = 0;

__device__ __forceinline__ float sigm(float x) { return 1.0f / (1.0f + expf(-x)); }

// SMEM layout (floats)
#define OFF_WS    0
#define OFF_PAN   (OFF_WS   + 576 * WS_STR)          // 41472
#define OFF_HN    (OFF_PAN  + 64 * PAN2_STR)         // 49920
#define OFF_WD    (OFF_HN   + JT * HN_STR)           // 51008
#define OFF_BSUM  (OFF_WD   + JT * C_)               // 53056
#define OFF_BD    (OFF_BSUM + 64)                    // 53120
#define OFF_RED   (OFF_BD   + C_)                    // 53248
#define SMEM_FLOATS (OFF_RED + 16)                   // 53264
#define SMEM_BYTES  (SMEM_FLOATS * 4)                // 213,056 B

typedef unsigned long long u64t;

__global__ void __launch_bounds__(NTHR, 1) lstm_persist_kernel(
    const float* __restrict__ X,    // [B, T, F]
    const float* __restrict__ Wih,  // [4H, F]
    const float* __restrict__ Whh,  // [4H, H]
    const float* __restrict__ bih,  // [4H]
    const float* __restrict__ bhh,  // [4H]
    const float* __restrict__ Wd,   // [C, H]
    const float* __restrict__ bd,   // [C]
    float* __restrict__ out)        // [B, T*C]
{
    extern __shared__ float sm[];
    float* ws   = sm + OFF_WS;    // [576][WS_STR]  row r = jj*4 + gate (i,f,g,o)
    float* hn   = sm + OFF_HN;    // [16][HN_STR]   h_new staging [jj][b]
    float* wd   = sm + OFF_WD;    // [16][128]      W_d slice [jj][c]
    float* bsum = sm + OFF_BSUM;  // [64]
    float* bds  = sm + OFF_BD;    // [128]
    float* red  = sm + OFF_RED;   // [16]

    const uint32_t smem_u32 = (uint32_t)__cvta_generic_to_shared(sm);
    const uint32_t ws_u32   = smem_u32 + OFF_WS  * 4;
    const uint32_t pan_u32  = smem_u32 + OFF_PAN * 4;

    const int tid = threadIdx.x;
    const int cta = blockIdx.x;
    const int jb  = cta & 31;         // h-chunk id
    const int bb  = cta >> 5;         // batch-chunk id
    const int J0  = jb * JT;
    const int b0  = bb * BT;
    const int tx  = tid & 15;         // jj index (4 gate rows)
    const int ty  = tid >> 4;         // batch quad index (0..15)
    const int wrp = tid >> 5;         // warp id (0..7)
    const int lane = tid & 31;

    // ---- one-time SMEM init: weights + biases (stationary for whole launch) ----
    for (int idx = tid; idx < 576 * 64; idx += NTHR) {
        int k = idx >> 6, r = idx & 63;
        int jj = r >> 2, g = r & 3;
        int grow = g * H_ + J0 + jj;             // PyTorch gate order i,f,g,o
        float v = (k < F_) ? Wih[(size_t)grow * F_ + k]
                           : Whh[(size_t)grow * H_ + (k - F_)];
        ws[k * WS_STR + r] = v;
    }
    for (int idx = tid; idx < JT * C_; idx += NTHR) {
        int jj = idx >> 7, c = idx & 127;
        wd[jj * C_ + c] = Wd[(size_t)c * H_ + J0 + jj];
    }
    if (tid < 64) {
        int jj = tid >> 2, g = tid & 3;
        bsum[tid] = bih[g * H_ + J0 + jj] + bhh[g * H_ + J0 + jj];
    }
    if (tid < C_) bds[tid] = bd[tid];

    float creg[4] = {0.f, 0.f, 0.f, 0.f};   // cell state: jj=tx, 4 batches (ty*4+q)

    // x prefetch registers (panel 0) and h prefetch registers
    float4 xr[4];
    float2 hr[8];
    {
        // prefetch x(t=0)
        int b_l = tid >> 2, q = tid & 3;
        const float* xp = X + ((size_t)(b0 + b_l) * T_) * F_ + q * 16;
        #pragma unroll
        for (int it = 0; it < 4; ++it) xr[it] = *(const float4*)(xp + it * 4);
    }
    __syncthreads();

    for (int t = 0; t < T_; ++t) {
        const int par = t & 1;

        // ---- stage panel 0 (x, duplicated) from prefetched regs ----
        {
            int b_l = tid >> 2, q = tid & 3;
            uint32_t base = pan_u32 + b_l * 8;   // bytes: 2*b_l floats
            #pragma unroll
            for (int it = 0; it < 4; ++it) {
                float4 v = xr[it];
                int k0 = q * 16 + it * 4;
                uint32_t a = base + (uint32_t)(k0 * PAN2_STR) * 4;
                asm volatile("st.shared.v2.f32 [%0], {%1,%1};" :: "r"(a),                       "f"(v.x));
                asm volatile("st.shared.v2.f32 [%0], {%1,%1};" :: "r"(a + PAN2_STR * 4),        "f"(v.y));
                asm volatile("st.shared.v2.f32 [%0], {%1,%1};" :: "r"(a + 2 * PAN2_STR * 4),    "f"(v.z));
                asm volatile("st.shared.v2.f32 [%0], {%1,%1};" :: "r"(a + 3 * PAN2_STR * 4),    "f"(v.w));
            }
        }
        // prefetch h panel 1 (rows 0..63 of hT) into hr
        #pragma unroll
        for (int i = 0; i < 8; ++i) {
            int row = wrp + 8 * i;
            hr[i] = __ldcg((const float2*)&g_hT[par][row][b0 + lane * 2]);
        }
        __syncthreads();

        // packed accumulators: a_if[b]=(gate_i,gate_f), a_go[b]=(gate_g,gate_o)
        u64t a_if0 = 0, a_if1 = 0, a_if2 = 0, a_if3 = 0;
        u64t a_go0 = 0, a_go1 = 0, a_go2 = 0, a_go3 = 0;

        for (int p = 0; p < 9; ++p) {
            // ---- compute panel p: 64 kk, packed f32x2 FMA ----
            {
                uint32_t wa = ws_u32 + (uint32_t)(p * 64 * WS_STR + tx * 4) * 4;
                uint32_t pa = pan_u32 + (uint32_t)(ty * 8) * 4;
                #pragma unroll 8
                for (int kk = 0; kk < 64; ++kk) {
                    u64t w_if, w_go, h0, h1, h2, h3;
                    asm volatile("ld.shared.v2.u64 {%0,%1}, [%2];"
                                 : "=l"(w_if), "=l"(w_go) : "r"(wa));
                    asm volatile("ld.shared.v2.u64 {%0,%1}, [%2];"
                                 : "=l"(h0), "=l"(h1) : "r"(pa));
                    asm volatile("ld.shared.v2.u64 {%0,%1}, [%2];"
                                 : "=l"(h2), "=l"(h3) : "r"(pa + 16));
                    asm("fma.rn.f32x2 %0, %1, %2, %0;" : "+l"(a_if0) : "l"(w_if), "l"(h0));
                    asm("fma.rn.f32x2 %0, %1, %2, %0;" : "+l"(a_go0) : "l"(w_go), "l"(h0));
                    asm("fma.rn.f32x2 %0, %1, %2, %0;" : "+l"(a_if1) : "l"(w_if), "l"(h1));
                    asm("fma.rn.f32x2 %0, %1, %2, %0;" : "+l"(a_go1) : "l"(w_go), "l"(h1));
                    asm("fma.rn.f32x2 %0, %1, %2, %0;" : "+l"(a_if2) : "l"(w_if), "l"(h2));
                    asm("fma.rn.f32x2 %0, %1, %2, %0;" : "+l"(a_go2) : "l"(w_go), "l"(h2));
                    asm("fma.rn.f32x2 %0, %1, %2, %0;" : "+l"(a_if3) : "l"(w_if), "l"(h3));
                    asm("fma.rn.f32x2 %0, %1, %2, %0;" : "+l"(a_go3) : "l"(w_go), "l"(h3));
                    wa += WS_STR * 4;
                    pa += PAN2_STR * 4;
                }
            }
            __syncthreads();   // everyone done reading pan

            if (p < 8) {
                // ---- store prefetched h panel p+1 (duplicated rows) ----
                #pragma unroll
                for (int i = 0; i < 8; ++i) {
                    int row = wrp + 8 * i;
                    uint32_t a = pan_u32 + (uint32_t)(row * PAN2_STR) * 4 + lane * 16;
                    asm volatile("st.shared.v4.f32 [%0], {%1,%1,%2,%2};"
                                 :: "r"(a), "f"(hr[i].x), "f"(hr[i].y));
                }
                // ---- prefetch h panel p+2 ----
                if (p + 1 < 8) {
                    #pragma unroll
                    for (int i = 0; i < 8; ++i) {
                        int row = wrp + 8 * i;
                        hr[i] = __ldcg((const float2*)&g_hT[par][(p + 1) * 64 + row][b0 + lane * 2]);
                    }
                }
                __syncthreads();  // pan ready for next panel
            }
        }

        // ---- cell update (c stays in registers) ----
        {
            u64t aif[4] = {a_if0, a_if1, a_if2, a_if3};
            u64t ago[4] = {a_go0, a_go1, a_go2, a_go3};
            #pragma unroll
            for (int bq = 0; bq < 4; ++bq) {
                float pi, pf, pg, po;
                asm("mov.b64 {%0,%1}, %2;" : "=f"(pi), "=f"(pf) : "l"(aif[bq]));
                asm("mov.b64 {%0,%1}, %2;" : "=f"(pg), "=f"(po) : "l"(ago[bq]));
                pi += bsum[tx * 4 + 0];
                pf += bsum[tx * 4 + 1];
                pg += bsum[tx * 4 + 2];
                po += bsum[tx * 4 + 3];
                float iv = sigm(pi), fv = sigm(pf), gv = tanhf(pg), ov = sigm(po);
                float cn = fv * creg[bq] + iv * gv;
                creg[bq] = cn;
                hn[tx * HN_STR + ty * 4 + bq] = ov * tanhf(cn);
            }
        }
        __syncthreads();

        // ---- write h_new to global (next parity buffer), coalesced ----
        {
            int row = tid >> 4, cq = tid & 15;
            float4 v = *(const float4*)(hn + row * HN_STR + cq * 4);
            *(float4*)(&g_hT[par ^ 1][J0 + row][b0 + cq * 4]) = v;
        }

        // ---- decoder partial logits from LOCAL h_new slice (relu fused) ----
        {
            int cq = tid >> 6, b_l = tid & 63;
            float accd[32];
            #pragma unroll
            for (int i = 0; i < 32; ++i) accd[i] = 0.f;
            #pragma unroll
            for (int kk = 0; kk < JT; ++kk) {
                float hv = fmaxf(hn[kk * HN_STR + b_l], 0.f);
                const float4* wp = (const float4*)(wd + kk * C_ + cq * 32);
                #pragma unroll
                for (int j = 0; j < 8; ++j) {
                    float4 w = wp[j];
                    accd[4 * j + 0] += w.x * hv; accd[4 * j + 1] += w.y * hv;
                    accd[4 * j + 2] += w.z * hv; accd[4 * j + 3] += w.w * hv;
                }
            }
            float4* dst = (float4*)(&g_part[par][jb][b0 + b_l][cq * 32]);
            #pragma unroll
            for (int j = 0; j < 8; ++j)
                dst[j] = make_float4(accd[4 * j + 0], accd[4 * j + 1],
                                     accd[4 * j + 2], accd[4 * j + 3]);
        }

        // ---- prefetch next step's x while we wait at the barrier ----
        if (t + 1 < T_) {
            int b_l = tid >> 2, q = tid & 3;
            const float* xp = X + ((size_t)(b0 + b_l) * T_ + (t + 1)) * F_ + q * 16;
            #pragma unroll
            for (int it = 0; it < 4; ++it) xr[it] = *(const float4*)(xp + it * 4);
        }

        // ---- grid-wide sync (sense-reversing; 2048/launch -> state resets) ----
        {
            unsigned target = (unsigned)((t & 1) ^ 1);
            __syncthreads();
            if (tid == 0) {
                __threadfence();                      // publish hT + partials to L2
                unsigned v = atomicAdd(&g_count, 1u);
                if (v == NCTA - 1) {
                    g_count = 0;
                    __threadfence();
                    g_sense = target;
                } else {
                    while (g_sense != target) { __nanosleep(64); }
                }
                __threadfence();
            }
            __syncthreads();
        }

        // ---- phase 4: reduce partials + softmax + write out (2 batches/CTA) ----
        {
            int half = tid >> 7;            // 0..1
            int c    = tid & 127;
            int b    = cta * 2 + half;
            float v = bds[c];
            #pragma unroll
            for (int j2 = 0; j2 < NJ; ++j2)
                v += __ldcg(&g_part[par][j2][b][c]);
            int wid2 = tid >> 5;
            float m = v;
            #pragma unroll
            for (int o = 16; o; o >>= 1)
                m = fmaxf(m, __shfl_xor_sync(0xffffffffu, m, o));
            if (lane == 0) red[wid2] = m;
            __syncthreads();
            float gm = fmaxf(fmaxf(red[half * 4 + 0], red[half * 4 + 1]),
                             fmaxf(red[half * 4 + 2], red[half * 4 + 3]));
            float e = expf(v - gm);
            float s = e;
            #pragma unroll
            for (int o = 16; o; o >>= 1)
                s += __shfl_xor_sync(0xffffffffu, s, o);
            if (lane == 0) red[8 + wid2] = s;
            __syncthreads();
            float gs = red[8 + half * 4 + 0] + red[8 + half * 4 + 1] +
                       red[8 + half * 4 + 2] + red[8 + half * 4 + 3];
            out[(size_t)b * (T_ * C_) + (size_t)t * C_ + c] = e / gs;
        }
        __syncthreads();
    }

    // ---- restore g_hT[0] to zeros so every launch/replay is identical ----
    {
        int row = tid >> 4, cq = tid & 15;
        *(float4*)(&g_hT[0][J0 + row][b0 + cq * 4]) = make_float4(0.f, 0.f, 0.f, 0.f);
    }
}

extern "C" void kernel_launch(void* const* d_in, const int* in_sizes, int n_in,
                              void* d_out, int out_size) {
    (void)in_sizes; (void)n_in; (void)out_size;
    const float* x   = (const float*)d_in[0];
    const float* Wih = (const float*)d_in[1];
    const float* Whh = (const float*)d_in[2];
    const float* bih = (const float*)d_in[3];
    const float* bhh = (const float*)d_in[4];
    const float* Wd  = (const float*)d_in[5];
    const float* bd  = (const float*)d_in[6];
    float* out = (float*)d_out;

    cudaFuncSetAttribute(lstm_persist_kernel,
                         cudaFuncAttributeMaxDynamicSharedMemorySize, SMEM_BYTES);
    lstm_persist_kernel<<<NCTA, NTHR, SMEM_BYTES>>>(x, Wih, Whh, bih, bhh, Wd, bd, out);
}